// round 14
// baseline (speedup 1.0000x reference)
#include <cuda_runtime.h>
#include <cuda_fp16.h>
#include <math.h>
#include <stdint.h>

#define NTOK (8 * 2048)      // 16384 rows
#define DIM  1024
#define NW   1152            // GEMM output width: 1024 Hx | 64 simH | 64 simL
#define MSL  64
#define KTOP 3
#define LN_EPS 1e-5f

// ---------------- scratch (allocation-free rule: __device__ globals) -------
__device__ __half g_xh[(size_t)NTOK * DIM];       // x rounded to fp16
__device__ __half g_B[(size_t)NW * DIM];          // [Wf_x ; Rh ; Rl] fp16
__device__ float g_bias[NW];                      // [bf | 0...]
__device__ float g_c[MSL];                        // mem @ bq
__device__ float g_P[(size_t)MSL * DIM];          // mem @ Wf_m^T (exact fp32)
__device__ float g_C[(size_t)NTOK * NW];          // GEMM out

// ---------------- helpers ----------------------------------------------------
__device__ __forceinline__ uint32_t smem_u32(const void* p) {
    uint32_t a;
    asm("{ .reg .u64 t; cvta.to.shared.u64 t, %1; cvt.u32.u64 %0, t; }" : "=r"(a) : "l"(p));
    return a;
}
__device__ __forceinline__ void cpasync16(uint32_t s, const void* g) {
    asm volatile("cp.async.cg.shared.global [%0], [%1], 16;" :: "r"(s), "l"(g));
}
__device__ __forceinline__ void cp_commit() {
    asm volatile("cp.async.commit_group;");
}
__device__ __forceinline__ void cp_wait2() {
    asm volatile("cp.async.wait_group 2;");
}
__device__ __forceinline__ void ldsm4(uint32_t* t, uint32_t addr) {
    asm volatile("ldmatrix.sync.aligned.m8n8.x4.shared.b16 {%0,%1,%2,%3}, [%4];"
        : "=r"(t[0]), "=r"(t[1]), "=r"(t[2]), "=r"(t[3]) : "r"(addr));
}
__device__ __forceinline__ void mma16816(float* d, const uint32_t* a,
                                         uint32_t b0, uint32_t b1) {
    asm volatile(
        "mma.sync.aligned.m16n8k16.row.col.f32.f16.f16.f32 "
        "{%0,%1,%2,%3}, {%4,%5,%6,%7}, {%8,%9}, {%0,%1,%2,%3};"
        : "+f"(d[0]), "+f"(d[1]), "+f"(d[2]), "+f"(d[3])
        : "r"(a[0]), "r"(a[1]), "r"(a[2]), "r"(a[3]), "r"(b0), "r"(b1));
}
// XOR swizzle for 128-row x 32-col fp16 tiles, 16B chunks (4/row), pitch 64B.
__device__ __forceinline__ uint32_t sw32(uint32_t row, uint32_t c) {
    return row * 64u + ((c ^ ((row >> 1) & 3u)) << 4);
}

// ---------------- round x -> fp16 (zero smem, full occupancy) -----------------
__global__ void __launch_bounds__(256) round_x_kernel(
    const float4* __restrict__ in, __half2* __restrict__ o)
{
    int i = blockIdx.x * 256 + threadIdx.x;
    float4 v = in[i];
    __half2 a; a.x = __float2half_rn(v.x); a.y = __float2half_rn(v.y);
    __half2 b; b.x = __float2half_rn(v.z); b.y = __float2half_rn(v.w);
    o[2 * i] = a; o[2 * i + 1] = b;
}

// ---------------- merged smem-prep kernel -------------------------------------
#define NB_PACKW (DIM * DIM / 4 / 256)    // 1024
#define NB_RPR   (64 * 8)                 // 512
#define NB_RPP   (64 * 8)                 // 512
#define NB_CVEC  8
#define NB_PREP  (NB_PACKW + NB_RPR + NB_RPP + NB_CVEC)

__global__ void __launch_bounds__(256) prep2_kernel(
    const float* __restrict__ mem,         // [64, 1024]
    const float* __restrict__ Wq,          // [1024, 1024]
    const float* __restrict__ bq,          // [1024]
    const float* __restrict__ Wf,          // [1024, 2048]
    const float* __restrict__ bf,          // [1024]
    __half2* __restrict__ B2,              // g_B as half2
    float* __restrict__ bias,
    float* __restrict__ P,
    float* __restrict__ c)
{
    __shared__ float sh[8 * DIM + 256];    // 33 KB
    const int tid = threadIdx.x;
    int b = blockIdx.x;

    if (b < NB_PACKW) {
        int i4 = b * 256 + tid;
        int d = i4 >> 8;
        int cc = (i4 & 255) * 4;
        float4 v = *reinterpret_cast<const float4*>(&Wf[(size_t)d * (2 * DIM) + cc]);
        __half2 a; a.x = __float2half_rn(v.x); a.y = __float2half_rn(v.y);
        __half2 e; e.x = __float2half_rn(v.z); e.y = __float2half_rn(v.w);
        B2[2 * i4] = a; B2[2 * i4 + 1] = e;
        if (i4 < NW) bias[i4] = (i4 < DIM) ? bf[i4] : 0.f;
        return;
    }
    b -= NB_PACKW;

    if (b < NB_RPR) {
        float* msf = sh;
        float* red = sh + 8 * DIM;
        const int c0 = (b & 63) * 16;
        const int m0 = (b >> 6) * 8;

        for (int i = tid; i < 8 * DIM; i += 256)
            msf[i] = mem[(size_t)(m0 + (i >> 10)) * DIM + (i & (DIM - 1))];
        __syncthreads();

        const int col = c0 + (tid & 15);
        const int m   = (tid >> 4) & 7;
        const int eg  = tid >> 7;
        const float* mrow = &msf[m * DIM + eg * 512];
        const float* wp = &Wq[(size_t)(eg * 512) * DIM + col];
        float acc = 0.f;
#pragma unroll 8
        for (int i = 0; i < 512; i++)
            acc = fmaf(mrow[i], wp[(size_t)i * DIM], acc);
        red[tid] = acc;
        __syncthreads();
        if (tid < 128) {
            float s = red[tid] + red[tid + 128];
            int mm = m0 + ((tid >> 4) & 7);
            int dd = c0 + (tid & 15);
            __half hi = __float2half_rn(s);
            __half lo = __float2half_rn(s - __half2float(hi));
            __half* B1 = reinterpret_cast<__half*>(B2);
            B1[(size_t)(DIM + mm) * DIM + dd] = hi;
            B1[(size_t)(DIM + MSL + mm) * DIM + dd] = lo;
        }
        return;
    }
    b -= NB_RPR;

    if (b < NB_RPP) {
        float* msf = sh;
        const int d0 = (b & 63) * 16;
        const int m0 = (b >> 6) * 8;

        for (int i = tid; i < 8 * DIM; i += 256)
            msf[i] = mem[(size_t)(m0 + (i >> 10)) * DIM + (i & (DIM - 1))];
        __syncthreads();

        const int d  = d0 + (tid >> 4);
        const int el = tid & 15;
        const float* wrow = &Wf[(size_t)d * (2 * DIM) + DIM];
        float acc[8];
#pragma unroll
        for (int j = 0; j < 8; j++) acc[j] = 0.f;
#pragma unroll 4
        for (int i = 0; i < 64; i++) {
            int e = el + i * 16;
            float w = wrow[e];
#pragma unroll
            for (int j = 0; j < 8; j++)
                acc[j] = fmaf(msf[j * DIM + e], w, acc[j]);
        }
#pragma unroll
        for (int o = 8; o; o >>= 1)
#pragma unroll
            for (int j = 0; j < 8; j++)
                acc[j] += __shfl_down_sync(0xffffffffu, acc[j], o, 16);
        if (el == 0) {
#pragma unroll
            for (int j = 0; j < 8; j++)
                P[(size_t)(m0 + j) * DIM + d] = acc[j];
        }
        return;
    }
    b -= NB_RPP;

    {
        const int warp = tid >> 5, lane = tid & 31;
        const int m = b * 8 + warp;
        const float4* mr = reinterpret_cast<const float4*>(mem + (size_t)m * DIM);
        const float4* bv = reinterpret_cast<const float4*>(bq);
        float s = 0.f;
#pragma unroll
        for (int i = 0; i < 8; i++) {
            float4 a = mr[lane + i * 32];
            float4 d = bv[lane + i * 32];
            s = fmaf(a.x, d.x, s); s = fmaf(a.y, d.y, s);
            s = fmaf(a.z, d.z, s); s = fmaf(a.w, d.w, s);
        }
#pragma unroll
        for (int o = 16; o; o >>= 1) s += __shfl_xor_sync(0xffffffffu, s, o);
        if (lane == 0) c[m] = s;
    }
}

// ---------------- fp16 HMMA GEMM: C = x16 @ B^T + bias ------------------------
// CTA 128(M) x 128(N), 4 warps of 64x64, BK=32, 4-stage ring (64 KB), 3 CTA/SM.
#define GBM 128
#define GBN 128
#define GBK 32
#define TILE_B 8192u
#define OFF_A  0u
#define OFF_B  (TILE_B)
#define STAGE_B (2u * TILE_B)             // 16 KB
#define NSTAGE 4
#define GEMM_SMEM (NSTAGE * STAGE_B)      // 64 KB

__global__ void __launch_bounds__(128, 3) gemm_fp16_kernel(
    const __half* __restrict__ A,
    const __half* __restrict__ B,
    const float* __restrict__ bias,
    float* __restrict__ C)
{
    extern __shared__ char smem[];
    const uint32_t sb = smem_u32(smem);
    const int tid = threadIdx.x;
    const int wid = tid >> 5;
    const int lane = tid & 31;
    const int n0 = blockIdx.y * GBM;
    const int e0 = blockIdx.x * GBN;
    const int nchunk = DIM / GBK;          // 32

    const uint32_t warp_m = (uint32_t)(wid >> 1) * 64u;   // 0 or 64
    const uint32_t warp_n = (uint32_t)(wid & 1) * 64u;    // 0 or 64

    float acc[4][8][4];
#pragma unroll
    for (int mt = 0; mt < 4; mt++)
#pragma unroll
        for (int nt = 0; nt < 8; nt++)
#pragma unroll
            for (int j = 0; j < 4; j++) acc[mt][nt][j] = 0.f;

    auto load_stage = [&](int i, int s) {
        const int kt = i * GBK;
        const uint32_t sbase = sb + (uint32_t)s * STAGE_B;
#pragma unroll
        for (int j = 0; j < 4; j++) {
            int g = tid + j * 128;                 // 0..511
            uint32_t r = (uint32_t)(g >> 2);
            uint32_t cc = (uint32_t)(g & 3);
            uint32_t so = sw32(r, cc);
            cpasync16(sbase + OFF_A + so, A + (size_t)(n0 + r) * DIM + kt + cc * 8);
            cpasync16(sbase + OFF_B + so, B + (size_t)(e0 + r) * DIM + kt + cc * 8);
        }
    };

    load_stage(0, 0); cp_commit();
    load_stage(1, 1); cp_commit();
    load_stage(2, 2); cp_commit();

    for (int i = 0; i < nchunk; i++) {
        cp_wait2();                 // stage i landed
        __syncthreads();
        if (i + 3 < nchunk) load_stage(i + 3, (i + 3) & 3);
        cp_commit();

        const uint32_t base = sb + (uint32_t)(i & 3) * STAGE_B;
#pragma unroll
        for (int k16 = 0; k16 < 2; k16++) {
            uint32_t af[4][4];
            const uint32_t arow = (uint32_t)(lane & 15);
            const uint32_t acnk = (uint32_t)(2 * k16 + (lane >> 4));
#pragma unroll
            for (int mt = 0; mt < 4; mt++) {
                uint32_t so = sw32(warp_m + (uint32_t)mt * 16u + arow, acnk);
                ldsm4(af[mt], base + OFF_A + so);
            }
            const uint32_t brow0 = (uint32_t)((lane & 7) + ((lane >> 4) & 1) * 8);
            const uint32_t bcnk  = (uint32_t)(2 * k16 + ((lane >> 3) & 1));
            // process B in n32 halves to bound live registers
#pragma unroll
            for (int nh = 0; nh < 2; nh++) {
                uint32_t bf16[4][2];
#pragma unroll
                for (int half = 0; half < 2; half++) {
                    uint32_t so = sw32(warp_n + (uint32_t)nh * 32u +
                                       (uint32_t)half * 16u + brow0, bcnk);
                    uint32_t t[4];
                    ldsm4(t, base + OFF_B + so);
                    bf16[2 * half][0] = t[0];     bf16[2 * half][1] = t[1];
                    bf16[2 * half + 1][0] = t[2]; bf16[2 * half + 1][1] = t[3];
                }
#pragma unroll
                for (int mt = 0; mt < 4; mt++) {
#pragma unroll
                    for (int j = 0; j < 4; j++)
                        mma16816(acc[mt][nh * 4 + j], af[mt],
                                 bf16[j][0], bf16[j][1]);
                }
            }
        }
    }

#pragma unroll
    for (int mt = 0; mt < 4; mt++) {
#pragma unroll
        for (int nt = 0; nt < 8; nt++) {
            int row = n0 + (int)warp_m + mt * 16 + (lane >> 2);
            int col = e0 + (int)warp_n + nt * 8 + (lane & 3) * 2;
            float b0 = bias[col], b1 = bias[col + 1];
            float2 v0; v0.x = acc[mt][nt][0] + b0; v0.y = acc[mt][nt][1] + b1;
            float2 v1; v1.x = acc[mt][nt][2] + b0; v1.y = acc[mt][nt][3] + b1;
            *reinterpret_cast<float2*>(&C[(size_t)row * NW + col]) = v0;
            *reinterpret_cast<float2*>(&C[(size_t)(row + 8) * NW + col]) = v1;
        }
    }
}

// ---------------- tail: warp-per-token, no barriers ---------------------------
__global__ void __launch_bounds__(256) tail_kernel(
    const float* __restrict__ C,           // [16384, 1152]
    const float* __restrict__ c,           // [64]
    const float* __restrict__ P,           // [64, 1024]
    const float* __restrict__ gamma,
    const float* __restrict__ beta,
    float* __restrict__ out)
{
    const int lane = threadIdx.x & 31;
    const int warp = threadIdx.x >> 5;
    const int n = blockIdx.x * 8 + warp;

    const float* crow = C + (size_t)n * NW;

    float s0 = crow[DIM + lane]      + crow[DIM + MSL + lane]      + c[lane];
    float s1 = crow[DIM + lane + 32] + crow[DIM + MSL + lane + 32] + c[lane + 32];

    float tv[KTOP]; int ti[KTOP];
#pragma unroll
    for (int r = 0; r < KTOP; r++) {
        float v; int idx;
        if (s0 >= s1) { v = s0; idx = lane; }
        else          { v = s1; idx = lane + 32; }
#pragma unroll
        for (int o = 16; o; o >>= 1) {
            float ov = __shfl_xor_sync(0xffffffffu, v, o);
            int   oi = __shfl_xor_sync(0xffffffffu, idx, o);
            if (ov > v || (ov == v && oi < idx)) { v = ov; idx = oi; }
        }
        tv[r] = v; ti[r] = idx;
        if (idx == lane)      s0 = -3.4e38f;
        if (idx == lane + 32) s1 = -3.4e38f;
    }
    float e1 = __expf(tv[1] - tv[0]);
    float e2 = __expf(tv[2] - tv[0]);
    float inv = 1.f / (1.f + e1 + e2);
    const float w0 = inv, w1 = e1 * inv, w2 = e2 * inv;

    const float4* c4 = reinterpret_cast<const float4*>(crow);
    const float4* p0 = reinterpret_cast<const float4*>(P + (size_t)ti[0] * DIM);
    const float4* p1 = reinterpret_cast<const float4*>(P + (size_t)ti[1] * DIM);
    const float4* p2 = reinterpret_cast<const float4*>(P + (size_t)ti[2] * DIM);

    float4 h[8];
    float s = 0.f, ss = 0.f;
#pragma unroll
    for (int i = 0; i < 8; i++) {
        int d = lane + i * 32;
        float4 v = c4[d];
        float4 a = p0[d], b = p1[d], e = p2[d];
        v.x += w0 * a.x + w1 * b.x + w2 * e.x;
        v.y += w0 * a.y + w1 * b.y + w2 * e.y;
        v.z += w0 * a.z + w1 * b.z + w2 * e.z;
        v.w += w0 * a.w + w1 * b.w + w2 * e.w;
        h[i] = v;
        s  += v.x + v.y + v.z + v.w;
        ss += v.x * v.x + v.y * v.y + v.z * v.z + v.w * v.w;
    }
#pragma unroll
    for (int o = 16; o; o >>= 1) {
        s  += __shfl_xor_sync(0xffffffffu, s, o);
        ss += __shfl_xor_sync(0xffffffffu, ss, o);
    }
    const float mean = s * (1.f / DIM);
    const float var  = ss * (1.f / DIM) - mean * mean;
    const float rstd = rsqrtf(var + LN_EPS);

    const float4* g4 = reinterpret_cast<const float4*>(gamma);
    const float4* b4 = reinterpret_cast<const float4*>(beta);
    float4* o4 = reinterpret_cast<float4*>(out + (size_t)n * DIM);
#pragma unroll
    for (int i = 0; i < 8; i++) {
        int d = lane + i * 32;
        float4 g = g4[d];
        float4 bb = b4[d];
        float4 v = h[i];
        float4 o;
        o.x = fmaxf((v.x - mean) * rstd * g.x + bb.x, 0.f);
        o.y = fmaxf((v.y - mean) * rstd * g.y + bb.y, 0.f);
        o.z = fmaxf((v.z - mean) * rstd * g.z + bb.z, 0.f);
        o.w = fmaxf((v.w - mean) * rstd * g.w + bb.w, 0.f);
        o4[d] = o;
    }
}

// ---------------- host --------------------------------------------------------
extern "C" void kernel_launch(void* const* d_in, const int* in_sizes, int n_in,
                              void* d_out, int out_size)
{
    const float* x      = (const float*)d_in[0];
    const float* memory = (const float*)d_in[1];
    const float* Wq     = (const float*)d_in[2];
    const float* bq     = (const float*)d_in[3];
    const float* Wf     = (const float*)d_in[4];
    const float* bf     = (const float*)d_in[5];
    const float* gamma  = (const float*)d_in[6];
    const float* beta   = (const float*)d_in[7];
    float* out = (float*)d_out;

    void *xh, *B, *bias, *c, *P, *C;
    cudaGetSymbolAddress(&xh, g_xh);
    cudaGetSymbolAddress(&B,  g_B);    cudaGetSymbolAddress(&bias, g_bias);
    cudaGetSymbolAddress(&c,  g_c);
    cudaGetSymbolAddress(&P,  g_P);    cudaGetSymbolAddress(&C,  g_C);

    static bool init_done = false;
    if (!init_done) {
        cudaFuncSetAttribute(gemm_fp16_kernel,
                             cudaFuncAttributeMaxDynamicSharedMemorySize, GEMM_SMEM);
        init_done = true;
    }

    // 1) round x (full occupancy, HBM-bound)
    round_x_kernel<<<NTOK * DIM / 4 / 256, 256>>>((const float4*)x, (__half2*)xh);

    // 2) merged smem-prep (L2-bound branches)
    prep2_kernel<<<NB_PREP, 256>>>(memory, Wq, bq, Wf, bf,
                                   (__half2*)B, (float*)bias, (float*)P, (float*)c);

    // 3) fused GEMM: C = x16 @ [Wf_x ; Rh ; Rl]^T + bias
    dim3 gg(NW / GBN, NTOK / GBM);   // (9, 128)
    gemm_fp16_kernel<<<gg, 128, GEMM_SMEM>>>(
        (const __half*)xh, (const __half*)B, (const float*)bias, (float*)C);

    // 4) tail: warp-per-token (no barriers)
    tail_kernel<<<NTOK / 8, 256>>>((const float*)C, (const float*)c,
                                   (const float*)P, gamma, beta, out);
}

// round 15
// speedup vs baseline: 1.0137x; 1.0137x over previous
#include <cuda_runtime.h>
#include <cuda_fp16.h>
#include <math.h>
#include <stdint.h>

#define NTOK (8 * 2048)      // 16384 rows
#define DIM  1024
#define NW   1152            // GEMM output width: 1024 Hx | 64 simH | 64 simL
#define MSL  64
#define KTOP 3
#define LN_EPS 1e-5f

// ---------------- scratch (allocation-free rule: __device__ globals) -------
__device__ __half g_xh[(size_t)NTOK * DIM];       // x rounded to fp16
__device__ __half g_B[(size_t)NW * DIM];          // [Wf_x ; Rh ; Rl] fp16
__device__ float g_bias[NW];                      // [bf | 0...]
__device__ float g_c[MSL];                        // mem @ bq
__device__ float g_P[(size_t)MSL * DIM];          // mem @ Wf_m^T (exact fp32)
__device__ __half g_C16[(size_t)NTOK * DIM];      // Hx in fp16
__device__ float g_Csim[(size_t)NTOK * 2 * MSL];  // sim strips fp32 [H|L]

// ---------------- helpers ----------------------------------------------------
__device__ __forceinline__ uint32_t smem_u32(const void* p) {
    uint32_t a;
    asm("{ .reg .u64 t; cvta.to.shared.u64 t, %1; cvt.u32.u64 %0, t; }" : "=r"(a) : "l"(p));
    return a;
}
__device__ __forceinline__ void cpasync16(uint32_t s, const void* g) {
    asm volatile("cp.async.cg.shared.global [%0], [%1], 16;" :: "r"(s), "l"(g));
}
__device__ __forceinline__ void cp_commit() {
    asm volatile("cp.async.commit_group;");
}
__device__ __forceinline__ void cp_wait4() {
    asm volatile("cp.async.wait_group 4;");
}
__device__ __forceinline__ void ldsm4(uint32_t* t, uint32_t addr) {
    asm volatile("ldmatrix.sync.aligned.m8n8.x4.shared.b16 {%0,%1,%2,%3}, [%4];"
        : "=r"(t[0]), "=r"(t[1]), "=r"(t[2]), "=r"(t[3]) : "r"(addr));
}
__device__ __forceinline__ void mma16816(float* d, const uint32_t* a,
                                         uint32_t b0, uint32_t b1) {
    asm volatile(
        "mma.sync.aligned.m16n8k16.row.col.f32.f16.f16.f32 "
        "{%0,%1,%2,%3}, {%4,%5,%6,%7}, {%8,%9}, {%0,%1,%2,%3};"
        : "+f"(d[0]), "+f"(d[1]), "+f"(d[2]), "+f"(d[3])
        : "r"(a[0]), "r"(a[1]), "r"(a[2]), "r"(a[3]), "r"(b0), "r"(b1));
}
// XOR swizzle for 128-row x 32-col fp16 tiles, 16B chunks (4/row), pitch 64B.
__device__ __forceinline__ uint32_t sw32(uint32_t row, uint32_t c) {
    return row * 64u + ((c ^ ((row >> 1) & 3u)) << 4);
}

// ---------------- round x -> fp16 (zero smem, full occupancy) -----------------
__global__ void __launch_bounds__(256) round_x_kernel(
    const float4* __restrict__ in, __half2* __restrict__ o)
{
    int i = blockIdx.x * 256 + threadIdx.x;
    float4 v = in[i];
    __half2 a; a.x = __float2half_rn(v.x); a.y = __float2half_rn(v.y);
    __half2 b; b.x = __float2half_rn(v.z); b.y = __float2half_rn(v.w);
    o[2 * i] = a; o[2 * i + 1] = b;
}

// ---------------- merged smem-prep kernel -------------------------------------
#define NB_PACKW (DIM * DIM / 4 / 256)    // 1024
#define NB_RPR   (64 * 8)                 // 512
#define NB_RPP   (64 * 8)                 // 512
#define NB_CVEC  8
#define NB_PREP  (NB_PACKW + NB_RPR + NB_RPP + NB_CVEC)

__global__ void __launch_bounds__(256) prep2_kernel(
    const float* __restrict__ mem,         // [64, 1024]
    const float* __restrict__ Wq,          // [1024, 1024]
    const float* __restrict__ bq,          // [1024]
    const float* __restrict__ Wf,          // [1024, 2048]
    const float* __restrict__ bf,          // [1024]
    __half2* __restrict__ B2,              // g_B as half2
    float* __restrict__ bias,
    float* __restrict__ P,
    float* __restrict__ c)
{
    __shared__ float sh[8 * DIM + 256];    // 33 KB
    const int tid = threadIdx.x;
    int b = blockIdx.x;

    if (b < NB_PACKW) {
        int i4 = b * 256 + tid;
        int d = i4 >> 8;
        int cc = (i4 & 255) * 4;
        float4 v = *reinterpret_cast<const float4*>(&Wf[(size_t)d * (2 * DIM) + cc]);
        __half2 a; a.x = __float2half_rn(v.x); a.y = __float2half_rn(v.y);
        __half2 e; e.x = __float2half_rn(v.z); e.y = __float2half_rn(v.w);
        B2[2 * i4] = a; B2[2 * i4 + 1] = e;
        if (i4 < NW) bias[i4] = (i4 < DIM) ? bf[i4] : 0.f;
        return;
    }
    b -= NB_PACKW;

    if (b < NB_RPR) {
        float* msf = sh;
        float* red = sh + 8 * DIM;
        const int c0 = (b & 63) * 16;
        const int m0 = (b >> 6) * 8;

        for (int i = tid; i < 8 * DIM; i += 256)
            msf[i] = mem[(size_t)(m0 + (i >> 10)) * DIM + (i & (DIM - 1))];
        __syncthreads();

        const int col = c0 + (tid & 15);
        const int m   = (tid >> 4) & 7;
        const int eg  = tid >> 7;
        const float* mrow = &msf[m * DIM + eg * 512];
        const float* wp = &Wq[(size_t)(eg * 512) * DIM + col];
        float acc = 0.f;
#pragma unroll 8
        for (int i = 0; i < 512; i++)
            acc = fmaf(mrow[i], wp[(size_t)i * DIM], acc);
        red[tid] = acc;
        __syncthreads();
        if (tid < 128) {
            float s = red[tid] + red[tid + 128];
            int mm = m0 + ((tid >> 4) & 7);
            int dd = c0 + (tid & 15);
            __half hi = __float2half_rn(s);
            __half lo = __float2half_rn(s - __half2float(hi));
            __half* B1 = reinterpret_cast<__half*>(B2);
            B1[(size_t)(DIM + mm) * DIM + dd] = hi;
            B1[(size_t)(DIM + MSL + mm) * DIM + dd] = lo;
        }
        return;
    }
    b -= NB_RPR;

    if (b < NB_RPP) {
        float* msf = sh;
        const int d0 = (b & 63) * 16;
        const int m0 = (b >> 6) * 8;

        for (int i = tid; i < 8 * DIM; i += 256)
            msf[i] = mem[(size_t)(m0 + (i >> 10)) * DIM + (i & (DIM - 1))];
        __syncthreads();

        const int d  = d0 + (tid >> 4);
        const int el = tid & 15;
        const float* wrow = &Wf[(size_t)d * (2 * DIM) + DIM];
        float acc[8];
#pragma unroll
        for (int j = 0; j < 8; j++) acc[j] = 0.f;
#pragma unroll 4
        for (int i = 0; i < 64; i++) {
            int e = el + i * 16;
            float w = wrow[e];
#pragma unroll
            for (int j = 0; j < 8; j++)
                acc[j] = fmaf(msf[j * DIM + e], w, acc[j]);
        }
#pragma unroll
        for (int o = 8; o; o >>= 1)
#pragma unroll
            for (int j = 0; j < 8; j++)
                acc[j] += __shfl_down_sync(0xffffffffu, acc[j], o, 16);
        if (el == 0) {
#pragma unroll
            for (int j = 0; j < 8; j++)
                P[(size_t)(m0 + j) * DIM + d] = acc[j];
        }
        return;
    }
    b -= NB_RPP;

    {
        const int warp = tid >> 5, lane = tid & 31;
        const int m = b * 8 + warp;
        const float4* mr = reinterpret_cast<const float4*>(mem + (size_t)m * DIM);
        const float4* bv = reinterpret_cast<const float4*>(bq);
        float s = 0.f;
#pragma unroll
        for (int i = 0; i < 8; i++) {
            float4 a = mr[lane + i * 32];
            float4 d = bv[lane + i * 32];
            s = fmaf(a.x, d.x, s); s = fmaf(a.y, d.y, s);
            s = fmaf(a.z, d.z, s); s = fmaf(a.w, d.w, s);
        }
#pragma unroll
        for (int o = 16; o; o >>= 1) s += __shfl_xor_sync(0xffffffffu, s, o);
        if (lane == 0) c[m] = s;
    }
}

// ---------------- fp16 HMMA GEMM (R13 proven shape) ---------------------------
// CTA 128x128, 8 warps of 64x32, BK=32, 6-stage ring (96 KB), 2 CTA/SM.
// Epilogue: Hx cols -> fp16 C16; sim cols (>=1024) -> fp32 Csim.
#define GBM 128
#define GBN 128
#define GBK 32
#define TILE_B 8192u
#define OFF_A  0u
#define OFF_B  (TILE_B)
#define STAGE_B (2u * TILE_B)             // 16 KB
#define NSTAGE 6
#define GEMM_SMEM (NSTAGE * STAGE_B)      // 96 KB

__global__ void __launch_bounds__(256, 2) gemm_fp16_kernel(
    const __half* __restrict__ A,
    const __half* __restrict__ B,
    const float* __restrict__ bias,
    __half* __restrict__ C16,              // [16384, 1024] fp16
    float* __restrict__ Csim)              // [16384, 128]  fp32
{
    extern __shared__ char smem[];
    const uint32_t sb = smem_u32(smem);
    const int tid = threadIdx.x;
    const int wid = tid >> 5;
    const int lane = tid & 31;
    const int n0 = blockIdx.y * GBM;
    const int e0 = blockIdx.x * GBN;
    const int nchunk = DIM / GBK;          // 32

    const uint32_t warp_m = (uint32_t)(wid >> 2) * 64u;
    const uint32_t warp_n = (uint32_t)(wid & 3) * 32u;

    float acc[4][4][4];
#pragma unroll
    for (int mt = 0; mt < 4; mt++)
#pragma unroll
        for (int nt = 0; nt < 4; nt++)
#pragma unroll
            for (int j = 0; j < 4; j++) acc[mt][nt][j] = 0.f;

    auto load_stage = [&](int i, int s) {
        const int kt = i * GBK;
        const uint32_t sbase = sb + (uint32_t)s * STAGE_B;
#pragma unroll
        for (int j = 0; j < 2; j++) {
            int g = tid + j * 256;
            uint32_t r = (uint32_t)(g >> 2);
            uint32_t cc = (uint32_t)(g & 3);
            uint32_t so = sw32(r, cc);
            cpasync16(sbase + OFF_A + so, A + (size_t)(n0 + r) * DIM + kt + cc * 8);
            cpasync16(sbase + OFF_B + so, B + (size_t)(e0 + r) * DIM + kt + cc * 8);
        }
    };

    load_stage(0, 0); cp_commit();
    load_stage(1, 1); cp_commit();
    load_stage(2, 2); cp_commit();
    load_stage(3, 3); cp_commit();
    load_stage(4, 4); cp_commit();

    int cs = 0;
    int ls = 5;
    for (int i = 0; i < nchunk; i++) {
        cp_wait4();
        __syncthreads();
        if (i + 5 < nchunk) load_stage(i + 5, ls);
        cp_commit();

        const uint32_t base = sb + (uint32_t)cs * STAGE_B;
#pragma unroll
        for (int k16 = 0; k16 < 2; k16++) {
            uint32_t af[4][4];
            const uint32_t arow = (uint32_t)(lane & 15);
            const uint32_t acnk = (uint32_t)(2 * k16 + (lane >> 4));
#pragma unroll
            for (int mt = 0; mt < 4; mt++) {
                uint32_t so = sw32(warp_m + (uint32_t)mt * 16u + arow, acnk);
                ldsm4(af[mt], base + OFF_A + so);
            }
            uint32_t bf16[4][2];
            const uint32_t brow0 = (uint32_t)((lane & 7) + ((lane >> 4) & 1) * 8);
            const uint32_t bcnk  = (uint32_t)(2 * k16 + ((lane >> 3) & 1));
#pragma unroll
            for (int half = 0; half < 2; half++) {
                uint32_t so = sw32(warp_n + (uint32_t)half * 16u + brow0, bcnk);
                uint32_t t[4];
                ldsm4(t, base + OFF_B + so);
                bf16[2 * half][0] = t[0];     bf16[2 * half][1] = t[1];
                bf16[2 * half + 1][0] = t[2]; bf16[2 * half + 1][1] = t[3];
            }
#pragma unroll
            for (int mt = 0; mt < 4; mt++) {
#pragma unroll
                for (int nt = 0; nt < 4; nt++)
                    mma16816(acc[mt][nt], af[mt], bf16[nt][0], bf16[nt][1]);
            }
        }
        cs = (cs + 1 == NSTAGE) ? 0 : cs + 1;
        ls = (ls + 1 == NSTAGE) ? 0 : ls + 1;
    }

#pragma unroll
    for (int mt = 0; mt < 4; mt++) {
#pragma unroll
        for (int nt = 0; nt < 4; nt++) {
            int row = n0 + (int)warp_m + mt * 16 + (lane >> 2);
            int col = e0 + (int)warp_n + nt * 8 + (lane & 3) * 2;
            float b0 = bias[col], b1 = bias[col + 1];
            float v00 = acc[mt][nt][0] + b0, v01 = acc[mt][nt][1] + b1;
            float v10 = acc[mt][nt][2] + b0, v11 = acc[mt][nt][3] + b1;
            if (col < DIM) {
                __half2 h0; h0.x = __float2half_rn(v00); h0.y = __float2half_rn(v01);
                __half2 h1; h1.x = __float2half_rn(v10); h1.y = __float2half_rn(v11);
                *reinterpret_cast<__half2*>(&C16[(size_t)row * DIM + col]) = h0;
                *reinterpret_cast<__half2*>(&C16[(size_t)(row + 8) * DIM + col]) = h1;
            } else {
                int sc = col - DIM;       // 0..127 (H strip 0..63, L strip 64..127)
                float2 f0; f0.x = v00; f0.y = v01;
                float2 f1; f1.x = v10; f1.y = v11;
                *reinterpret_cast<float2*>(&Csim[(size_t)row * (2 * MSL) + sc]) = f0;
                *reinterpret_cast<float2*>(&Csim[(size_t)(row + 8) * (2 * MSL) + sc]) = f1;
            }
        }
    }
}

// ---------------- tail: warp-per-token, fp16 Hx, no barriers ------------------
__global__ void __launch_bounds__(256) tail_kernel(
    const __half* __restrict__ C16,        // [16384, 1024] fp16
    const float* __restrict__ Csim,        // [16384, 128]
    const float* __restrict__ c,           // [64]
    const float* __restrict__ P,           // [64, 1024]
    const float* __restrict__ gamma,
    const float* __restrict__ beta,
    float* __restrict__ out)
{
    const int lane = threadIdx.x & 31;
    const int warp = threadIdx.x >> 5;
    const int n = blockIdx.x * 8 + warp;

    const float* srow = Csim + (size_t)n * (2 * MSL);
    float s0 = srow[lane]      + srow[MSL + lane]      + c[lane];
    float s1 = srow[lane + 32] + srow[MSL + lane + 32] + c[lane + 32];

    float tv[KTOP]; int ti[KTOP];
#pragma unroll
    for (int r = 0; r < KTOP; r++) {
        float v; int idx;
        if (s0 >= s1) { v = s0; idx = lane; }
        else          { v = s1; idx = lane + 32; }
#pragma unroll
        for (int o = 16; o; o >>= 1) {
            float ov = __shfl_xor_sync(0xffffffffu, v, o);
            int   oi = __shfl_xor_sync(0xffffffffu, idx, o);
            if (ov > v || (ov == v && oi < idx)) { v = ov; idx = oi; }
        }
        tv[r] = v; ti[r] = idx;
        if (idx == lane)      s0 = -3.4e38f;
        if (idx == lane + 32) s1 = -3.4e38f;
    }
    float e1 = __expf(tv[1] - tv[0]);
    float e2 = __expf(tv[2] - tv[0]);
    float inv = 1.f / (1.f + e1 + e2);
    const float w0 = inv, w1 = e1 * inv, w2 = e2 * inv;

    const uint4* cu = reinterpret_cast<const uint4*>(C16 + (size_t)n * DIM); // 128/row
    const float4* p0 = reinterpret_cast<const float4*>(P + (size_t)ti[0] * DIM);
    const float4* p1 = reinterpret_cast<const float4*>(P + (size_t)ti[1] * DIM);
    const float4* p2 = reinterpret_cast<const float4*>(P + (size_t)ti[2] * DIM);

    float4 h[8];                 // 32 floats per lane
    float s = 0.f, ss = 0.f;
#pragma unroll
    for (int i = 0; i < 4; i++) {
        int q = lane + i * 32;           // uint4 index (8 halves)
        uint4 u = cu[q];
        const __half2* ph = reinterpret_cast<const __half2*>(&u);
#pragma unroll
        for (int half = 0; half < 2; half++) {
            int d = 2 * q + half;            // float4 index
            float2 fa = __half22float2(ph[2 * half]);
            float2 fb = __half22float2(ph[2 * half + 1]);
            float4 v; v.x = fa.x; v.y = fa.y; v.z = fb.x; v.w = fb.y;
            float4 a = p0[d], b = p1[d], e = p2[d];
            v.x += w0 * a.x + w1 * b.x + w2 * e.x;
            v.y += w0 * a.y + w1 * b.y + w2 * e.y;
            v.z += w0 * a.z + w1 * b.z + w2 * e.z;
            v.w += w0 * a.w + w1 * b.w + w2 * e.w;
            h[2 * i + half] = v;
            s  += v.x + v.y + v.z + v.w;
            ss += v.x * v.x + v.y * v.y + v.z * v.z + v.w * v.w;
        }
    }
#pragma unroll
    for (int o = 16; o; o >>= 1) {
        s  += __shfl_xor_sync(0xffffffffu, s, o);
        ss += __shfl_xor_sync(0xffffffffu, ss, o);
    }
    const float mean = s * (1.f / DIM);
    const float var  = ss * (1.f / DIM) - mean * mean;
    const float rstd = rsqrtf(var + LN_EPS);

    const float4* g4 = reinterpret_cast<const float4*>(gamma);
    const float4* b4 = reinterpret_cast<const float4*>(beta);
    float4* o4 = reinterpret_cast<float4*>(out + (size_t)n * DIM);
#pragma unroll
    for (int i = 0; i < 8; i++) {
        int d = 2 * (lane + (i >> 1) * 32) + (i & 1);
        float4 g = g4[d];
        float4 bb = b4[d];
        float4 v = h[i];
        float4 o;
        o.x = fmaxf((v.x - mean) * rstd * g.x + bb.x, 0.f);
        o.y = fmaxf((v.y - mean) * rstd * g.y + bb.y, 0.f);
        o.z = fmaxf((v.z - mean) * rstd * g.z + bb.z, 0.f);
        o.w = fmaxf((v.w - mean) * rstd * g.w + bb.w, 0.f);
        o4[d] = o;
    }
}

// ---------------- host --------------------------------------------------------
extern "C" void kernel_launch(void* const* d_in, const int* in_sizes, int n_in,
                              void* d_out, int out_size)
{
    const float* x      = (const float*)d_in[0];
    const float* memory = (const float*)d_in[1];
    const float* Wq     = (const float*)d_in[2];
    const float* bq     = (const float*)d_in[3];
    const float* Wf     = (const float*)d_in[4];
    const float* bf     = (const float*)d_in[5];
    const float* gamma  = (const float*)d_in[6];
    const float* beta   = (const float*)d_in[7];
    float* out = (float*)d_out;

    void *xh, *B, *bias, *c, *P, *C16, *Csim;
    cudaGetSymbolAddress(&xh,  g_xh);
    cudaGetSymbolAddress(&B,   g_B);    cudaGetSymbolAddress(&bias, g_bias);
    cudaGetSymbolAddress(&c,   g_c);    cudaGetSymbolAddress(&P,    g_P);
    cudaGetSymbolAddress(&C16, g_C16);  cudaGetSymbolAddress(&Csim, g_Csim);

    static bool init_done = false;
    if (!init_done) {
        cudaFuncSetAttribute(gemm_fp16_kernel,
                             cudaFuncAttributeMaxDynamicSharedMemorySize, GEMM_SMEM);
        init_done = true;
    }

    // 1) round x (full occupancy, HBM-bound)
    round_x_kernel<<<NTOK * DIM / 4 / 256, 256>>>((const float4*)x, (__half2*)xh);

    // 2) merged smem-prep (L2-bound branches)
    prep2_kernel<<<NB_PREP, 256>>>(memory, Wq, bq, Wf, bf,
                                   (__half2*)B, (float*)bias, (float*)P, (float*)c);

    // 3) fused GEMM: Hx -> fp16, sim strips -> fp32
    dim3 gg(NW / GBN, NTOK / GBM);   // (9, 128)
    gemm_fp16_kernel<<<gg, 256, GEMM_SMEM>>>(
        (const __half*)xh, (const __half*)B, (const float*)bias,
        (__half*)C16, (float*)Csim);

    // 4) tail: warp-per-token (no barriers)
    tail_kernel<<<NTOK / 8, 256>>>((const __half*)C16, (const float*)Csim,
                                   (const float*)c, (const float*)P,
                                   gamma, beta, out);
}

// round 16
// speedup vs baseline: 1.0530x; 1.0387x over previous
#include <cuda_runtime.h>
#include <cuda_fp16.h>
#include <math.h>
#include <stdint.h>

#define NTOK (8 * 2048)      // 16384 rows
#define DIM  1024
#define NW   1152            // GEMM output width: 1024 Hx | 64 simH | 64 simL
#define MSL  64
#define KTOP 3
#define LN_EPS 1e-5f

// ---------------- scratch (allocation-free rule: __device__ globals) -------
__device__ __half g_xh[(size_t)NTOK * DIM];       // x rounded to fp16
__device__ __half g_B[(size_t)NW * DIM];          // [Wf_x ; Rh ; Rl] fp16
__device__ float g_bias[NW];                      // [bf | 0...]
__device__ float g_c[MSL];                        // mem @ bq
__device__ float g_P[(size_t)MSL * DIM];          // mem @ Wf_m^T (exact fp32)
__device__ __half g_C16[(size_t)NTOK * DIM];      // Hx in fp16
__device__ float g_Csim[(size_t)NTOK * 2 * MSL];  // sim strips fp32 [H|L]

// ---------------- helpers ----------------------------------------------------
__device__ __forceinline__ uint32_t smem_u32(const void* p) {
    uint32_t a;
    asm("{ .reg .u64 t; cvta.to.shared.u64 t, %1; cvt.u32.u64 %0, t; }" : "=r"(a) : "l"(p));
    return a;
}
__device__ __forceinline__ void cpasync16(uint32_t s, const void* g) {
    asm volatile("cp.async.cg.shared.global [%0], [%1], 16;" :: "r"(s), "l"(g));
}
__device__ __forceinline__ void cp_commit() {
    asm volatile("cp.async.commit_group;");
}
__device__ __forceinline__ void cp_wait4() {
    asm volatile("cp.async.wait_group 4;");
}
__device__ __forceinline__ void ldsm4(uint32_t* t, uint32_t addr) {
    asm volatile("ldmatrix.sync.aligned.m8n8.x4.shared.b16 {%0,%1,%2,%3}, [%4];"
        : "=r"(t[0]), "=r"(t[1]), "=r"(t[2]), "=r"(t[3]) : "r"(addr));
}
__device__ __forceinline__ void mma16816(float* d, const uint32_t* a,
                                         uint32_t b0, uint32_t b1) {
    asm volatile(
        "mma.sync.aligned.m16n8k16.row.col.f32.f16.f16.f32 "
        "{%0,%1,%2,%3}, {%4,%5,%6,%7}, {%8,%9}, {%0,%1,%2,%3};"
        : "+f"(d[0]), "+f"(d[1]), "+f"(d[2]), "+f"(d[3])
        : "r"(a[0]), "r"(a[1]), "r"(a[2]), "r"(a[3]), "r"(b0), "r"(b1));
}
// XOR swizzle for 128-row x 32-col fp16 tiles, 16B chunks (4/row), pitch 64B.
__device__ __forceinline__ uint32_t sw32(uint32_t row, uint32_t c) {
    return row * 64u + ((c ^ ((row >> 1) & 3u)) << 4);
}

// ---------------- round x -> fp16 (zero smem, full occupancy) -----------------
__global__ void __launch_bounds__(256) round_x_kernel(
    const float4* __restrict__ in, __half2* __restrict__ o)
{
    int i = blockIdx.x * 256 + threadIdx.x;
    float4 v = in[i];
    __half2 a; a.x = __float2half_rn(v.x); a.y = __float2half_rn(v.y);
    __half2 b; b.x = __float2half_rn(v.z); b.y = __float2half_rn(v.w);
    o[2 * i] = a; o[2 * i + 1] = b;
}

// ---------------- merged smem-prep kernel -------------------------------------
#define NB_PACKW (DIM * DIM / 4 / 256)    // 1024
#define NB_RPR   (64 * 8)                 // 512
#define NB_RPP   (64 * 8)                 // 512
#define NB_CVEC  8
#define NB_PREP  (NB_PACKW + NB_RPR + NB_RPP + NB_CVEC)

__global__ void __launch_bounds__(256) prep2_kernel(
    const float* __restrict__ mem,         // [64, 1024]
    const float* __restrict__ Wq,          // [1024, 1024]
    const float* __restrict__ bq,          // [1024]
    const float* __restrict__ Wf,          // [1024, 2048]
    const float* __restrict__ bf,          // [1024]
    __half2* __restrict__ B2,              // g_B as half2
    float* __restrict__ bias,
    float* __restrict__ P,
    float* __restrict__ c)
{
    __shared__ float sh[8 * DIM + 256];    // 33 KB
    const int tid = threadIdx.x;
    int b = blockIdx.x;

    if (b < NB_PACKW) {
        int i4 = b * 256 + tid;
        int d = i4 >> 8;
        int cc = (i4 & 255) * 4;
        float4 v = *reinterpret_cast<const float4*>(&Wf[(size_t)d * (2 * DIM) + cc]);
        __half2 a; a.x = __float2half_rn(v.x); a.y = __float2half_rn(v.y);
        __half2 e; e.x = __float2half_rn(v.z); e.y = __float2half_rn(v.w);
        B2[2 * i4] = a; B2[2 * i4 + 1] = e;
        if (i4 < NW) bias[i4] = (i4 < DIM) ? bf[i4] : 0.f;
        return;
    }
    b -= NB_PACKW;

    if (b < NB_RPR) {
        float* msf = sh;
        float* red = sh + 8 * DIM;
        const int c0 = (b & 63) * 16;
        const int m0 = (b >> 6) * 8;

        for (int i = tid; i < 8 * DIM; i += 256)
            msf[i] = mem[(size_t)(m0 + (i >> 10)) * DIM + (i & (DIM - 1))];
        __syncthreads();

        const int col = c0 + (tid & 15);
        const int m   = (tid >> 4) & 7;
        const int eg  = tid >> 7;
        const float* mrow = &msf[m * DIM + eg * 512];
        const float* wp = &Wq[(size_t)(eg * 512) * DIM + col];
        float acc = 0.f;
#pragma unroll 8
        for (int i = 0; i < 512; i++)
            acc = fmaf(mrow[i], wp[(size_t)i * DIM], acc);
        red[tid] = acc;
        __syncthreads();
        if (tid < 128) {
            float s = red[tid] + red[tid + 128];
            int mm = m0 + ((tid >> 4) & 7);
            int dd = c0 + (tid & 15);
            __half hi = __float2half_rn(s);
            __half lo = __float2half_rn(s - __half2float(hi));
            __half* B1 = reinterpret_cast<__half*>(B2);
            B1[(size_t)(DIM + mm) * DIM + dd] = hi;
            B1[(size_t)(DIM + MSL + mm) * DIM + dd] = lo;
        }
        return;
    }
    b -= NB_RPR;

    if (b < NB_RPP) {
        float* msf = sh;
        const int d0 = (b & 63) * 16;
        const int m0 = (b >> 6) * 8;

        for (int i = tid; i < 8 * DIM; i += 256)
            msf[i] = mem[(size_t)(m0 + (i >> 10)) * DIM + (i & (DIM - 1))];
        __syncthreads();

        const int d  = d0 + (tid >> 4);
        const int el = tid & 15;
        const float* wrow = &Wf[(size_t)d * (2 * DIM) + DIM];
        float acc[8];
#pragma unroll
        for (int j = 0; j < 8; j++) acc[j] = 0.f;
#pragma unroll 4
        for (int i = 0; i < 64; i++) {
            int e = el + i * 16;
            float w = wrow[e];
#pragma unroll
            for (int j = 0; j < 8; j++)
                acc[j] = fmaf(msf[j * DIM + e], w, acc[j]);
        }
#pragma unroll
        for (int o = 8; o; o >>= 1)
#pragma unroll
            for (int j = 0; j < 8; j++)
                acc[j] += __shfl_down_sync(0xffffffffu, acc[j], o, 16);
        if (el == 0) {
#pragma unroll
            for (int j = 0; j < 8; j++)
                P[(size_t)(m0 + j) * DIM + d] = acc[j];
        }
        return;
    }
    b -= NB_RPP;

    {
        const int warp = tid >> 5, lane = tid & 31;
        const int m = b * 8 + warp;
        const float4* mr = reinterpret_cast<const float4*>(mem + (size_t)m * DIM);
        const float4* bv = reinterpret_cast<const float4*>(bq);
        float s = 0.f;
#pragma unroll
        for (int i = 0; i < 8; i++) {
            float4 a = mr[lane + i * 32];
            float4 d = bv[lane + i * 32];
            s = fmaf(a.x, d.x, s); s = fmaf(a.y, d.y, s);
            s = fmaf(a.z, d.z, s); s = fmaf(a.w, d.w, s);
        }
#pragma unroll
        for (int o = 16; o; o >>= 1) s += __shfl_xor_sync(0xffffffffu, s, o);
        if (lane == 0) c[m] = s;
    }
}

// ---------------- fp16 HMMA GEMM (R13 proven shape) ---------------------------
#define GBM 128
#define GBN 128
#define GBK 32
#define TILE_B 8192u
#define OFF_A  0u
#define OFF_B  (TILE_B)
#define STAGE_B (2u * TILE_B)             // 16 KB
#define NSTAGE 6
#define GEMM_SMEM (NSTAGE * STAGE_B)      // 96 KB

__global__ void __launch_bounds__(256, 2) gemm_fp16_kernel(
    const __half* __restrict__ A,
    const __half* __restrict__ B,
    const float* __restrict__ bias,
    __half* __restrict__ C16,              // [16384, 1024] fp16
    float* __restrict__ Csim)              // [16384, 128]  fp32
{
    extern __shared__ char smem[];
    const uint32_t sb = smem_u32(smem);
    const int tid = threadIdx.x;
    const int wid = tid >> 5;
    const int lane = tid & 31;
    const int n0 = blockIdx.y * GBM;
    const int e0 = blockIdx.x * GBN;
    const int nchunk = DIM / GBK;          // 32

    const uint32_t warp_m = (uint32_t)(wid >> 2) * 64u;
    const uint32_t warp_n = (uint32_t)(wid & 3) * 32u;

    float acc[4][4][4];
#pragma unroll
    for (int mt = 0; mt < 4; mt++)
#pragma unroll
        for (int nt = 0; nt < 4; nt++)
#pragma unroll
            for (int j = 0; j < 4; j++) acc[mt][nt][j] = 0.f;

    auto load_stage = [&](int i, int s) {
        const int kt = i * GBK;
        const uint32_t sbase = sb + (uint32_t)s * STAGE_B;
#pragma unroll
        for (int j = 0; j < 2; j++) {
            int g = tid + j * 256;
            uint32_t r = (uint32_t)(g >> 2);
            uint32_t cc = (uint32_t)(g & 3);
            uint32_t so = sw32(r, cc);
            cpasync16(sbase + OFF_A + so, A + (size_t)(n0 + r) * DIM + kt + cc * 8);
            cpasync16(sbase + OFF_B + so, B + (size_t)(e0 + r) * DIM + kt + cc * 8);
        }
    };

    load_stage(0, 0); cp_commit();
    load_stage(1, 1); cp_commit();
    load_stage(2, 2); cp_commit();
    load_stage(3, 3); cp_commit();
    load_stage(4, 4); cp_commit();

    int cs = 0;
    int ls = 5;
    for (int i = 0; i < nchunk; i++) {
        cp_wait4();
        __syncthreads();
        if (i + 5 < nchunk) load_stage(i + 5, ls);
        cp_commit();

        const uint32_t base = sb + (uint32_t)cs * STAGE_B;
#pragma unroll
        for (int k16 = 0; k16 < 2; k16++) {
            uint32_t af[4][4];
            const uint32_t arow = (uint32_t)(lane & 15);
            const uint32_t acnk = (uint32_t)(2 * k16 + (lane >> 4));
#pragma unroll
            for (int mt = 0; mt < 4; mt++) {
                uint32_t so = sw32(warp_m + (uint32_t)mt * 16u + arow, acnk);
                ldsm4(af[mt], base + OFF_A + so);
            }
            uint32_t bf16[4][2];
            const uint32_t brow0 = (uint32_t)((lane & 7) + ((lane >> 4) & 1) * 8);
            const uint32_t bcnk  = (uint32_t)(2 * k16 + ((lane >> 3) & 1));
#pragma unroll
            for (int half = 0; half < 2; half++) {
                uint32_t so = sw32(warp_n + (uint32_t)half * 16u + brow0, bcnk);
                uint32_t t[4];
                ldsm4(t, base + OFF_B + so);
                bf16[2 * half][0] = t[0];     bf16[2 * half][1] = t[1];
                bf16[2 * half + 1][0] = t[2]; bf16[2 * half + 1][1] = t[3];
            }
#pragma unroll
            for (int mt = 0; mt < 4; mt++) {
#pragma unroll
                for (int nt = 0; nt < 4; nt++)
                    mma16816(acc[mt][nt], af[mt], bf16[nt][0], bf16[nt][1]);
            }
        }
        cs = (cs + 1 == NSTAGE) ? 0 : cs + 1;
        ls = (ls + 1 == NSTAGE) ? 0 : ls + 1;
    }

#pragma unroll
    for (int mt = 0; mt < 4; mt++) {
#pragma unroll
        for (int nt = 0; nt < 4; nt++) {
            int row = n0 + (int)warp_m + mt * 16 + (lane >> 2);
            int col = e0 + (int)warp_n + nt * 8 + (lane & 3) * 2;
            float b0 = bias[col], b1 = bias[col + 1];
            float v00 = acc[mt][nt][0] + b0, v01 = acc[mt][nt][1] + b1;
            float v10 = acc[mt][nt][2] + b0, v11 = acc[mt][nt][3] + b1;
            if (col < DIM) {
                __half2 h0; h0.x = __float2half_rn(v00); h0.y = __float2half_rn(v01);
                __half2 h1; h1.x = __float2half_rn(v10); h1.y = __float2half_rn(v11);
                *reinterpret_cast<__half2*>(&C16[(size_t)row * DIM + col]) = h0;
                *reinterpret_cast<__half2*>(&C16[(size_t)(row + 8) * DIM + col]) = h1;
            } else {
                int sc = col - DIM;       // 0..127 (H strip 0..63, L strip 64..127)
                float2 f0; f0.x = v00; f0.y = v01;
                float2 f1; f1.x = v10; f1.y = v11;
                *reinterpret_cast<float2*>(&Csim[(size_t)row * (2 * MSL) + sc]) = f0;
                *reinterpret_cast<float2*>(&Csim[(size_t)(row + 8) * (2 * MSL) + sc]) = f1;
            }
        }
    }
}

// ---------------- tail: warp-per-token, fp16 Hx, coalesced walk ---------------
__global__ void __launch_bounds__(256) tail_kernel(
    const __half* __restrict__ C16,        // [16384, 1024] fp16
    const float* __restrict__ Csim,        // [16384, 128]
    const float* __restrict__ c,           // [64]
    const float* __restrict__ P,           // [64, 1024]
    const float* __restrict__ gamma,
    const float* __restrict__ beta,
    float* __restrict__ out)
{
    const int lane = threadIdx.x & 31;
    const int warp = threadIdx.x >> 5;
    const int n = blockIdx.x * 8 + warp;

    const float* srow = Csim + (size_t)n * (2 * MSL);
    float s0 = srow[lane]      + srow[MSL + lane]      + c[lane];
    float s1 = srow[lane + 32] + srow[MSL + lane + 32] + c[lane + 32];

    float tv[KTOP]; int ti[KTOP];
#pragma unroll
    for (int r = 0; r < KTOP; r++) {
        float v; int idx;
        if (s0 >= s1) { v = s0; idx = lane; }
        else          { v = s1; idx = lane + 32; }
#pragma unroll
        for (int o = 16; o; o >>= 1) {
            float ov = __shfl_xor_sync(0xffffffffu, v, o);
            int   oi = __shfl_xor_sync(0xffffffffu, idx, o);
            if (ov > v || (ov == v && oi < idx)) { v = ov; idx = oi; }
        }
        tv[r] = v; ti[r] = idx;
        if (idx == lane)      s0 = -3.4e38f;
        if (idx == lane + 32) s1 = -3.4e38f;
    }
    float e1 = __expf(tv[1] - tv[0]);
    float e2 = __expf(tv[2] - tv[0]);
    float inv = 1.f / (1.f + e1 + e2);
    const float w0 = inv, w1 = e1 * inv, w2 = e2 * inv;

    // coalesced walk: d = lane + j*32 (float4 granularity), C16 read as uint2
    const uint2*  cu2 = reinterpret_cast<const uint2*>(C16 + (size_t)n * DIM);
    const float4* p0 = reinterpret_cast<const float4*>(P + (size_t)ti[0] * DIM);
    const float4* p1 = reinterpret_cast<const float4*>(P + (size_t)ti[1] * DIM);
    const float4* p2 = reinterpret_cast<const float4*>(P + (size_t)ti[2] * DIM);

    float4 h[8];
    float s = 0.f, ss = 0.f;
#pragma unroll
    for (int j = 0; j < 8; j++) {
        int d = lane + j * 32;
        uint2 u = cu2[d];
        float2 fa = __half22float2(*reinterpret_cast<const __half2*>(&u.x));
        float2 fb = __half22float2(*reinterpret_cast<const __half2*>(&u.y));
        float4 v; v.x = fa.x; v.y = fa.y; v.z = fb.x; v.w = fb.y;
        float4 a = p0[d], b = p1[d], e = p2[d];
        v.x += w0 * a.x + w1 * b.x + w2 * e.x;
        v.y += w0 * a.y + w1 * b.y + w2 * e.y;
        v.z += w0 * a.z + w1 * b.z + w2 * e.z;
        v.w += w0 * a.w + w1 * b.w + w2 * e.w;
        h[j] = v;
        s  += v.x + v.y + v.z + v.w;
        ss += v.x * v.x + v.y * v.y + v.z * v.z + v.w * v.w;
    }
#pragma unroll
    for (int o = 16; o; o >>= 1) {
        s  += __shfl_xor_sync(0xffffffffu, s, o);
        ss += __shfl_xor_sync(0xffffffffu, ss, o);
    }
    const float mean = s * (1.f / DIM);
    const float var  = ss * (1.f / DIM) - mean * mean;
    const float rstd = rsqrtf(var + LN_EPS);

    const float4* g4 = reinterpret_cast<const float4*>(gamma);
    const float4* b4 = reinterpret_cast<const float4*>(beta);
    float4* o4 = reinterpret_cast<float4*>(out + (size_t)n * DIM);
#pragma unroll
    for (int j = 0; j < 8; j++) {
        int d = lane + j * 32;
        float4 g = g4[d];
        float4 bb = b4[d];
        float4 v = h[j];
        float4 o;
        o.x = fmaxf((v.x - mean) * rstd * g.x + bb.x, 0.f);
        o.y = fmaxf((v.y - mean) * rstd * g.y + bb.y, 0.f);
        o.z = fmaxf((v.z - mean) * rstd * g.z + bb.z, 0.f);
        o.w = fmaxf((v.w - mean) * rstd * g.w + bb.w, 0.f);
        o4[d] = o;
    }
}

// ---------------- host --------------------------------------------------------
extern "C" void kernel_launch(void* const* d_in, const int* in_sizes, int n_in,
                              void* d_out, int out_size)
{
    const float* x      = (const float*)d_in[0];
    const float* memory = (const float*)d_in[1];
    const float* Wq     = (const float*)d_in[2];
    const float* bq     = (const float*)d_in[3];
    const float* Wf     = (const float*)d_in[4];
    const float* bf     = (const float*)d_in[5];
    const float* gamma  = (const float*)d_in[6];
    const float* beta   = (const float*)d_in[7];
    float* out = (float*)d_out;

    void *xh, *B, *bias, *c, *P, *C16, *Csim;
    cudaGetSymbolAddress(&xh,  g_xh);
    cudaGetSymbolAddress(&B,   g_B);    cudaGetSymbolAddress(&bias, g_bias);
    cudaGetSymbolAddress(&c,   g_c);    cudaGetSymbolAddress(&P,    g_P);
    cudaGetSymbolAddress(&C16, g_C16);  cudaGetSymbolAddress(&Csim, g_Csim);

    static bool init_done = false;
    if (!init_done) {
        cudaFuncSetAttribute(gemm_fp16_kernel,
                             cudaFuncAttributeMaxDynamicSharedMemorySize, GEMM_SMEM);
        init_done = true;
    }

    // 1) round x (full occupancy, HBM-bound)
    round_x_kernel<<<NTOK * DIM / 4 / 256, 256>>>((const float4*)x, (__half2*)xh);

    // 2) merged smem-prep (L2-bound branches)
    prep2_kernel<<<NB_PREP, 256>>>(memory, Wq, bq, Wf, bf,
                                   (__half2*)B, (float*)bias, (float*)P, (float*)c);

    // 3) fused GEMM: Hx -> fp16, sim strips -> fp32
    dim3 gg(NW / GBN, NTOK / GBM);   // (9, 128)
    gemm_fp16_kernel<<<gg, 256, GEMM_SMEM>>>(
        (const __half*)xh, (const __half*)B, (const float*)bias,
        (__half*)C16, (float*)Csim);

    // 4) tail: warp-per-token (coalesced)
    tail_kernel<<<NTOK / 8, 256>>>((const __half*)C16, (const float*)Csim,
                                   (const float*)c, (const float*)P,
                                   gamma, beta, out);
}

// round 17
// speedup vs baseline: 1.0684x; 1.0146x over previous
#include <cuda_runtime.h>
#include <cuda_fp16.h>
#include <math.h>
#include <stdint.h>

#define NTOK (8 * 2048)      // 16384 rows
#define DIM  1024
#define NW   1152            // GEMM output width: 1024 Hx | 64 simH | 64 simL
#define MSL  64
#define KTOP 3
#define LN_EPS 1e-5f

// ---------------- scratch (allocation-free rule: __device__ globals) -------
__device__ __half g_xh[(size_t)NTOK * DIM];       // x rounded to fp16
__device__ __half g_B[(size_t)NW * DIM];          // [Wf_x ; Rh ; Rl] fp16
__device__ float g_bias[NW];                      // [bf | 0...]
__device__ float g_c[MSL];                        // mem @ bq
__device__ float g_P[(size_t)MSL * DIM];          // mem @ Wf_m^T (exact fp32)
__device__ __half g_C16[(size_t)NTOK * DIM];      // Hx in fp16
__device__ float g_Csim[(size_t)NTOK * 2 * MSL];  // sim strips fp32 [H|L]

// ---------------- helpers ----------------------------------------------------
__device__ __forceinline__ uint32_t smem_u32(const void* p) {
    uint32_t a;
    asm("{ .reg .u64 t; cvta.to.shared.u64 t, %1; cvt.u32.u64 %0, t; }" : "=r"(a) : "l"(p));
    return a;
}
__device__ __forceinline__ void cpasync16(uint32_t s, const void* g) {
    asm volatile("cp.async.cg.shared.global [%0], [%1], 16;" :: "r"(s), "l"(g));
}
__device__ __forceinline__ void cp_commit() {
    asm volatile("cp.async.commit_group;");
}
__device__ __forceinline__ void cp_wait4() {
    asm volatile("cp.async.wait_group 4;");
}
__device__ __forceinline__ void ldsm4(uint32_t* t, uint32_t addr) {
    asm volatile("ldmatrix.sync.aligned.m8n8.x4.shared.b16 {%0,%1,%2,%3}, [%4];"
        : "=r"(t[0]), "=r"(t[1]), "=r"(t[2]), "=r"(t[3]) : "r"(addr));
}
__device__ __forceinline__ void mma16816(float* d, const uint32_t* a,
                                         uint32_t b0, uint32_t b1) {
    asm volatile(
        "mma.sync.aligned.m16n8k16.row.col.f32.f16.f16.f32 "
        "{%0,%1,%2,%3}, {%4,%5,%6,%7}, {%8,%9}, {%0,%1,%2,%3};"
        : "+f"(d[0]), "+f"(d[1]), "+f"(d[2]), "+f"(d[3])
        : "r"(a[0]), "r"(a[1]), "r"(a[2]), "r"(a[3]), "r"(b0), "r"(b1));
}
// XOR swizzle for 128-row x 32-col fp16 tiles, 16B chunks (4/row), pitch 64B.
__device__ __forceinline__ uint32_t sw32(uint32_t row, uint32_t c) {
    return row * 64u + ((c ^ ((row >> 1) & 3u)) << 4);
}
// order-preserving float -> u32 map and exact inverse
__device__ __forceinline__ uint32_t mono_f2u(float f) {
    uint32_t u = __float_as_uint(f);
    return (u & 0x80000000u) ? ~u : (u | 0x80000000u);
}
__device__ __forceinline__ float mono_u2f(uint32_t u) {
    return (u & 0x80000000u) ? __uint_as_float(u & 0x7FFFFFFFu)
                             : __uint_as_float(~u);
}

// ---------------- round x -> fp16 (zero smem, full occupancy) -----------------
__global__ void __launch_bounds__(256) round_x_kernel(
    const float4* __restrict__ in, __half2* __restrict__ o)
{
    int i = blockIdx.x * 256 + threadIdx.x;
    float4 v = in[i];
    __half2 a; a.x = __float2half_rn(v.x); a.y = __float2half_rn(v.y);
    __half2 b; b.x = __float2half_rn(v.z); b.y = __float2half_rn(v.w);
    o[2 * i] = a; o[2 * i + 1] = b;
}

// ---------------- merged smem-prep kernel -------------------------------------
#define NB_PACKW (DIM * DIM / 4 / 256)    // 1024
#define NB_RPR   (64 * 8)                 // 512
#define NB_RPP   (64 * 8)                 // 512
#define NB_CVEC  8
#define NB_PREP  (NB_PACKW + NB_RPR + NB_RPP + NB_CVEC)

__global__ void __launch_bounds__(256) prep2_kernel(
    const float* __restrict__ mem,         // [64, 1024]
    const float* __restrict__ Wq,          // [1024, 1024]
    const float* __restrict__ bq,          // [1024]
    const float* __restrict__ Wf,          // [1024, 2048]
    const float* __restrict__ bf,          // [1024]
    __half2* __restrict__ B2,              // g_B as half2
    float* __restrict__ bias,
    float* __restrict__ P,
    float* __restrict__ c)
{
    __shared__ float sh[8 * DIM + 256];    // 33 KB
    const int tid = threadIdx.x;
    int b = blockIdx.x;

    if (b < NB_PACKW) {
        int i4 = b * 256 + tid;
        int d = i4 >> 8;
        int cc = (i4 & 255) * 4;
        float4 v = *reinterpret_cast<const float4*>(&Wf[(size_t)d * (2 * DIM) + cc]);
        __half2 a; a.x = __float2half_rn(v.x); a.y = __float2half_rn(v.y);
        __half2 e; e.x = __float2half_rn(v.z); e.y = __float2half_rn(v.w);
        B2[2 * i4] = a; B2[2 * i4 + 1] = e;
        if (i4 < NW) bias[i4] = (i4 < DIM) ? bf[i4] : 0.f;
        return;
    }
    b -= NB_PACKW;

    if (b < NB_RPR) {
        float* msf = sh;
        float* red = sh + 8 * DIM;
        const int c0 = (b & 63) * 16;
        const int m0 = (b >> 6) * 8;

        for (int i = tid; i < 8 * DIM; i += 256)
            msf[i] = mem[(size_t)(m0 + (i >> 10)) * DIM + (i & (DIM - 1))];
        __syncthreads();

        const int col = c0 + (tid & 15);
        const int m   = (tid >> 4) & 7;
        const int eg  = tid >> 7;
        const float* mrow = &msf[m * DIM + eg * 512];
        const float* wp = &Wq[(size_t)(eg * 512) * DIM + col];
        float acc = 0.f;
#pragma unroll 8
        for (int i = 0; i < 512; i++)
            acc = fmaf(mrow[i], wp[(size_t)i * DIM], acc);
        red[tid] = acc;
        __syncthreads();
        if (tid < 128) {
            float s = red[tid] + red[tid + 128];
            int mm = m0 + ((tid >> 4) & 7);
            int dd = c0 + (tid & 15);
            __half hi = __float2half_rn(s);
            __half lo = __float2half_rn(s - __half2float(hi));
            __half* B1 = reinterpret_cast<__half*>(B2);
            B1[(size_t)(DIM + mm) * DIM + dd] = hi;
            B1[(size_t)(DIM + MSL + mm) * DIM + dd] = lo;
        }
        return;
    }
    b -= NB_RPR;

    if (b < NB_RPP) {
        float* msf = sh;
        const int d0 = (b & 63) * 16;
        const int m0 = (b >> 6) * 8;

        for (int i = tid; i < 8 * DIM; i += 256)
            msf[i] = mem[(size_t)(m0 + (i >> 10)) * DIM + (i & (DIM - 1))];
        __syncthreads();

        const int d  = d0 + (tid >> 4);
        const int el = tid & 15;
        const float* wrow = &Wf[(size_t)d * (2 * DIM) + DIM];
        float acc[8];
#pragma unroll
        for (int j = 0; j < 8; j++) acc[j] = 0.f;
#pragma unroll 4
        for (int i = 0; i < 64; i++) {
            int e = el + i * 16;
            float w = wrow[e];
#pragma unroll
            for (int j = 0; j < 8; j++)
                acc[j] = fmaf(msf[j * DIM + e], w, acc[j]);
        }
#pragma unroll
        for (int o = 8; o; o >>= 1)
#pragma unroll
            for (int j = 0; j < 8; j++)
                acc[j] += __shfl_down_sync(0xffffffffu, acc[j], o, 16);
        if (el == 0) {
#pragma unroll
            for (int j = 0; j < 8; j++)
                P[(size_t)(m0 + j) * DIM + d] = acc[j];
        }
        return;
    }
    b -= NB_RPP;

    {
        const int warp = tid >> 5, lane = tid & 31;
        const int m = b * 8 + warp;
        const float4* mr = reinterpret_cast<const float4*>(mem + (size_t)m * DIM);
        const float4* bv = reinterpret_cast<const float4*>(bq);
        float s = 0.f;
#pragma unroll
        for (int i = 0; i < 8; i++) {
            float4 a = mr[lane + i * 32];
            float4 d = bv[lane + i * 32];
            s = fmaf(a.x, d.x, s); s = fmaf(a.y, d.y, s);
            s = fmaf(a.z, d.z, s); s = fmaf(a.w, d.w, s);
        }
#pragma unroll
        for (int o = 16; o; o >>= 1) s += __shfl_xor_sync(0xffffffffu, s, o);
        if (lane == 0) c[m] = s;
    }
}

// ---------------- fp16 HMMA GEMM (R13 proven shape) ---------------------------
#define GBM 128
#define GBN 128
#define GBK 32
#define TILE_B 8192u
#define OFF_A  0u
#define OFF_B  (TILE_B)
#define STAGE_B (2u * TILE_B)             // 16 KB
#define NSTAGE 6
#define GEMM_SMEM (NSTAGE * STAGE_B)      // 96 KB

__global__ void __launch_bounds__(256, 2) gemm_fp16_kernel(
    const __half* __restrict__ A,
    const __half* __restrict__ B,
    const float* __restrict__ bias,
    __half* __restrict__ C16,              // [16384, 1024] fp16
    float* __restrict__ Csim)              // [16384, 128]  fp32
{
    extern __shared__ char smem[];
    const uint32_t sb = smem_u32(smem);
    const int tid = threadIdx.x;
    const int wid = tid >> 5;
    const int lane = tid & 31;
    const int n0 = blockIdx.y * GBM;
    const int e0 = blockIdx.x * GBN;
    const int nchunk = DIM / GBK;          // 32

    const uint32_t warp_m = (uint32_t)(wid >> 2) * 64u;
    const uint32_t warp_n = (uint32_t)(wid & 3) * 32u;

    float acc[4][4][4];
#pragma unroll
    for (int mt = 0; mt < 4; mt++)
#pragma unroll
        for (int nt = 0; nt < 4; nt++)
#pragma unroll
            for (int j = 0; j < 4; j++) acc[mt][nt][j] = 0.f;

    auto load_stage = [&](int i, int s) {
        const int kt = i * GBK;
        const uint32_t sbase = sb + (uint32_t)s * STAGE_B;
#pragma unroll
        for (int j = 0; j < 2; j++) {
            int g = tid + j * 256;
            uint32_t r = (uint32_t)(g >> 2);
            uint32_t cc = (uint32_t)(g & 3);
            uint32_t so = sw32(r, cc);
            cpasync16(sbase + OFF_A + so, A + (size_t)(n0 + r) * DIM + kt + cc * 8);
            cpasync16(sbase + OFF_B + so, B + (size_t)(e0 + r) * DIM + kt + cc * 8);
        }
    };

    load_stage(0, 0); cp_commit();
    load_stage(1, 1); cp_commit();
    load_stage(2, 2); cp_commit();
    load_stage(3, 3); cp_commit();
    load_stage(4, 4); cp_commit();

    int cs = 0;
    int ls = 5;
    for (int i = 0; i < nchunk; i++) {
        cp_wait4();
        __syncthreads();
        if (i + 5 < nchunk) load_stage(i + 5, ls);
        cp_commit();

        const uint32_t base = sb + (uint32_t)cs * STAGE_B;
#pragma unroll
        for (int k16 = 0; k16 < 2; k16++) {
            uint32_t af[4][4];
            const uint32_t arow = (uint32_t)(lane & 15);
            const uint32_t acnk = (uint32_t)(2 * k16 + (lane >> 4));
#pragma unroll
            for (int mt = 0; mt < 4; mt++) {
                uint32_t so = sw32(warp_m + (uint32_t)mt * 16u + arow, acnk);
                ldsm4(af[mt], base + OFF_A + so);
            }
            uint32_t bf16[4][2];
            const uint32_t brow0 = (uint32_t)((lane & 7) + ((lane >> 4) & 1) * 8);
            const uint32_t bcnk  = (uint32_t)(2 * k16 + ((lane >> 3) & 1));
#pragma unroll
            for (int half = 0; half < 2; half++) {
                uint32_t so = sw32(warp_n + (uint32_t)half * 16u + brow0, bcnk);
                uint32_t t[4];
                ldsm4(t, base + OFF_B + so);
                bf16[2 * half][0] = t[0];     bf16[2 * half][1] = t[1];
                bf16[2 * half + 1][0] = t[2]; bf16[2 * half + 1][1] = t[3];
            }
#pragma unroll
            for (int mt = 0; mt < 4; mt++) {
#pragma unroll
                for (int nt = 0; nt < 4; nt++)
                    mma16816(acc[mt][nt], af[mt], bf16[nt][0], bf16[nt][1]);
            }
        }
        cs = (cs + 1 == NSTAGE) ? 0 : cs + 1;
        ls = (ls + 1 == NSTAGE) ? 0 : ls + 1;
    }

#pragma unroll
    for (int mt = 0; mt < 4; mt++) {
#pragma unroll
        for (int nt = 0; nt < 4; nt++) {
            int row = n0 + (int)warp_m + mt * 16 + (lane >> 2);
            int col = e0 + (int)warp_n + nt * 8 + (lane & 3) * 2;
            float b0 = bias[col], b1 = bias[col + 1];
            float v00 = acc[mt][nt][0] + b0, v01 = acc[mt][nt][1] + b1;
            float v10 = acc[mt][nt][2] + b0, v11 = acc[mt][nt][3] + b1;
            if (col < DIM) {
                __half2 h0; h0.x = __float2half_rn(v00); h0.y = __float2half_rn(v01);
                __half2 h1; h1.x = __float2half_rn(v10); h1.y = __float2half_rn(v11);
                *reinterpret_cast<__half2*>(&C16[(size_t)row * DIM + col]) = h0;
                *reinterpret_cast<__half2*>(&C16[(size_t)(row + 8) * DIM + col]) = h1;
            } else {
                int sc = col - DIM;
                float2 f0; f0.x = v00; f0.y = v01;
                float2 f1; f1.x = v10; f1.y = v11;
                *reinterpret_cast<float2*>(&Csim[(size_t)row * (2 * MSL) + sc]) = f0;
                *reinterpret_cast<float2*>(&Csim[(size_t)(row + 8) * (2 * MSL) + sc]) = f1;
            }
        }
    }
}

// ---------------- tail: warp-per-token, prefetch + redux top3 -----------------
__global__ void __launch_bounds__(256) tail_kernel(
    const __half* __restrict__ C16,        // [16384, 1024] fp16
    const float* __restrict__ Csim,        // [16384, 128]
    const float* __restrict__ c,           // [64]
    const float* __restrict__ P,           // [64, 1024]
    const float* __restrict__ gamma,
    const float* __restrict__ beta,
    float* __restrict__ out)
{
    const int lane = threadIdx.x & 31;
    const int warp = threadIdx.x >> 5;
    const int n = blockIdx.x * 8 + warp;

    // ---- prefetch C16 row (independent of everything below) ----
    const uint2* cu2 = reinterpret_cast<const uint2*>(C16 + (size_t)n * DIM);
    uint2 upre[8];
#pragma unroll
    for (int j = 0; j < 8; j++) upre[j] = cu2[lane + j * 32];

    // ---- sim + top3 (redux argmax, ties -> lowest index) ----
    const float* srow = Csim + (size_t)n * (2 * MSL);
    float s0 = srow[lane]      + srow[MSL + lane]      + c[lane];
    float s1 = srow[lane + 32] + srow[MSL + lane + 32] + c[lane + 32];
    uint32_t m0 = mono_f2u(s0);
    uint32_t m1 = mono_f2u(s1);

    float tv[KTOP]; int ti[KTOP];
#pragma unroll
    for (int r = 0; r < KTOP; r++) {
        uint32_t loc = m0 > m1 ? m0 : m1;
        uint32_t win = __reduce_max_sync(0xffffffffu, loc);
        uint32_t b0 = __ballot_sync(0xffffffffu, m0 == win);
        uint32_t b1 = __ballot_sync(0xffffffffu, m1 == win);
        int idx = b0 ? (__ffs(b0) - 1) : (__ffs(b1) + 31);
        tv[r] = mono_u2f(win); ti[r] = idx;
        if (idx == lane)      m0 = 0;
        if (idx == lane + 32) m1 = 0;
    }
    float e1 = __expf(tv[1] - tv[0]);
    float e2 = __expf(tv[2] - tv[0]);
    float inv = 1.f / (1.f + e1 + e2);
    const float w0 = inv, w1 = e1 * inv, w2 = e2 * inv;

    // ---- gather P + fuse + LN sums (coalesced walk) ----
    const float4* p0 = reinterpret_cast<const float4*>(P + (size_t)ti[0] * DIM);
    const float4* p1 = reinterpret_cast<const float4*>(P + (size_t)ti[1] * DIM);
    const float4* p2 = reinterpret_cast<const float4*>(P + (size_t)ti[2] * DIM);

    float4 h[8];
    float s = 0.f, ss = 0.f;
#pragma unroll
    for (int j = 0; j < 8; j++) {
        int d = lane + j * 32;
        float2 fa = __half22float2(*reinterpret_cast<const __half2*>(&upre[j].x));
        float2 fb = __half22float2(*reinterpret_cast<const __half2*>(&upre[j].y));
        float4 v; v.x = fa.x; v.y = fa.y; v.z = fb.x; v.w = fb.y;
        float4 a = p0[d], b = p1[d], e = p2[d];
        v.x += w0 * a.x + w1 * b.x + w2 * e.x;
        v.y += w0 * a.y + w1 * b.y + w2 * e.y;
        v.z += w0 * a.z + w1 * b.z + w2 * e.z;
        v.w += w0 * a.w + w1 * b.w + w2 * e.w;
        h[j] = v;
        s  += v.x + v.y + v.z + v.w;
        ss += v.x * v.x + v.y * v.y + v.z * v.z + v.w * v.w;
    }
#pragma unroll
    for (int o = 16; o; o >>= 1) {
        s  += __shfl_xor_sync(0xffffffffu, s, o);
        ss += __shfl_xor_sync(0xffffffffu, ss, o);
    }
    const float mean = s * (1.f / DIM);
    const float var  = ss * (1.f / DIM) - mean * mean;
    const float rstd = rsqrtf(var + LN_EPS);

    const float4* g4 = reinterpret_cast<const float4*>(gamma);
    const float4* b4 = reinterpret_cast<const float4*>(beta);
    float4* o4 = reinterpret_cast<float4*>(out + (size_t)n * DIM);
#pragma unroll
    for (int j = 0; j < 8; j++) {
        int d = lane + j * 32;
        float4 g = g4[d];
        float4 bb = b4[d];
        float4 v = h[j];
        float4 o;
        o.x = fmaxf((v.x - mean) * rstd * g.x + bb.x, 0.f);
        o.y = fmaxf((v.y - mean) * rstd * g.y + bb.y, 0.f);
        o.z = fmaxf((v.z - mean) * rstd * g.z + bb.z, 0.f);
        o.w = fmaxf((v.w - mean) * rstd * g.w + bb.w, 0.f);
        o4[d] = o;
    }
}

// ---------------- host --------------------------------------------------------
extern "C" void kernel_launch(void* const* d_in, const int* in_sizes, int n_in,
                              void* d_out, int out_size)
{
    const float* x      = (const float*)d_in[0];
    const float* memory = (const float*)d_in[1];
    const float* Wq     = (const float*)d_in[2];
    const float* bq     = (const float*)d_in[3];
    const float* Wf     = (const float*)d_in[4];
    const float* bf     = (const float*)d_in[5];
    const float* gamma  = (const float*)d_in[6];
    const float* beta   = (const float*)d_in[7];
    float* out = (float*)d_out;

    void *xh, *B, *bias, *c, *P, *C16, *Csim;
    cudaGetSymbolAddress(&xh,  g_xh);
    cudaGetSymbolAddress(&B,   g_B);    cudaGetSymbolAddress(&bias, g_bias);
    cudaGetSymbolAddress(&c,   g_c);    cudaGetSymbolAddress(&P,    g_P);
    cudaGetSymbolAddress(&C16, g_C16);  cudaGetSymbolAddress(&Csim, g_Csim);

    static bool init_done = false;
    if (!init_done) {
        cudaFuncSetAttribute(gemm_fp16_kernel,
                             cudaFuncAttributeMaxDynamicSharedMemorySize, GEMM_SMEM);
        init_done = true;
    }

    // 1) round x (full occupancy, HBM-bound)
    round_x_kernel<<<NTOK * DIM / 4 / 256, 256>>>((const float4*)x, (__half2*)xh);

    // 2) merged smem-prep (L2-bound branches)
    prep2_kernel<<<NB_PREP, 256>>>(memory, Wq, bq, Wf, bf,
                                   (__half2*)B, (float*)bias, (float*)P, (float*)c);

    // 3) fused GEMM: Hx -> fp16, sim strips -> fp32
    dim3 gg(NW / GBN, NTOK / GBM);   // (9, 128)
    gemm_fp16_kernel<<<gg, 256, GEMM_SMEM>>>(
        (const __half*)xh, (const __half*)B, (const float*)bias,
        (__half*)C16, (float*)Csim);

    // 4) tail: warp-per-token, prefetch + redux top3
    tail_kernel<<<NTOK / 8, 256>>>((const __half*)C16, (const float*)Csim,
                                   (const float*)c, (const float*)P,
                                   gamma, beta, out);
}